// round 3
// baseline (speedup 1.0000x reference)
#include <cuda_runtime.h>

// Problem constants (fixed shapes)
#define BB 32
#define NN 65536
#define MM 64
#define BLOCKS_PER_B (NN / 256)          // 256
#define GRID_MAIN (BB * BLOCKS_PER_B)    // 8192

__device__ __constant__ float EPSF = 1e-6f;

// Scratch (static device globals; no allocation)
__device__ unsigned long long g_bg[(size_t)BB * NN];   // per-pred packed (best_iou_bits<<32)|best_gt_idx
__device__ unsigned long long g_pg[BB * MM];           // per-gt packed (iou_bits<<32)|(0xFFFFFFFF - pred_idx)
__device__ float g_part[GRID_MAIN * 4];                // per-block partial sums (fl, vcnt, gsum, pcnt)
__device__ float g_bres[BB * 3];                       // per-batch cls, reg, pcnt

// ---------------------------------------------------------------------------
__global__ void k_init() {
    int i = blockIdx.x * blockDim.x + threadIdx.x;
    if (i < BB * MM) g_pg[i] = 0ull;
}

// ---------------------------------------------------------------------------
// Pass 1: pairwise IoU. One thread per prediction.
__global__ void __launch_bounds__(256) k_pass1(const float* __restrict__ pred,
                                               const float* __restrict__ gt) {
    const int b = blockIdx.x >> 8;
    const int n = ((blockIdx.x & 255) << 8) | threadIdx.x;
    const int tid = threadIdx.x;

    __shared__ float4 sg[MM];
    __shared__ float sa[MM];
    __shared__ unsigned long long smax[MM];

    if (tid < MM) {
        float4 g = ((const float4*)(gt + (size_t)b * MM * 4))[tid];
        sg[tid] = g;
        sa[tid] = (g.z - g.x) * (g.w - g.y);
        smax[tid] = 0ull;
    }
    __syncthreads();

    const float* p = pred + ((size_t)b * NN + n) * 5;
    const float cx = p[0], cy = p[1], w = p[2], h = p[3];
    const float px1 = cx - w * 0.5f, py1 = cy - h * 0.5f;
    const float px2 = cx + w * 0.5f, py2 = cy + h * 0.5f;
    const float parea = (px2 - px1) * (py2 - py1);

    float bestI = -1.0f;
    int bestM = 0;
    const unsigned long long packLow =
        (unsigned long long)(0xFFFFFFFFu - (unsigned)n);  // smaller n -> larger packed (tie-break)

#pragma unroll 8
    for (int m = 0; m < MM; ++m) {
        float4 g = sg[m];
        float x1 = fmaxf(px1, g.x);
        float y1 = fmaxf(py1, g.y);
        float x2 = fminf(px2, g.z);
        float y2 = fminf(py2, g.w);
        float iw = fmaxf(x2 - x1, 0.0f);
        float ih = fmaxf(y2 - y1, 0.0f);
        float inter = iw * ih;
        float uni = parea + sa[m] - inter;
        float iou = inter / fmaxf(uni, EPSF);   // IEEE divide, matches XLA
        if (iou > bestI) { bestI = iou; bestM = m; }
        if (iou > 0.1f) {                       // only pairs >0.1 can influence pos_scatter
            unsigned long long pk =
                ((unsigned long long)__float_as_uint(iou) << 32) | packLow;
            atomicMax(&smax[m], pk);
        }
    }

    // bestI >= 0 always (first iteration updates from -1)
    g_bg[(size_t)b * NN + n] =
        ((unsigned long long)__float_as_uint(bestI) << 32) | (unsigned)bestM;

    __syncthreads();
    if (tid < MM && smax[tid])
        atomicMax(&g_pg[b * MM + tid], smax[tid]);
}

// ---------------------------------------------------------------------------
// Pass 2: focal + giou, per-block deterministic reduction.
__global__ void __launch_bounds__(256) k_pass2(const float* __restrict__ pred,
                                               const float* __restrict__ gt) {
    const int b = blockIdx.x >> 8;
    const int blk = blockIdx.x & 255;
    const int tid = threadIdx.x;
    const int n = (blk << 8) | tid;

    __shared__ float4 sg[MM];
    __shared__ unsigned char sflag[256];

    sflag[tid] = 0;
    if (tid < MM)
        sg[tid] = ((const float4*)(gt + (size_t)b * MM * 4))[tid];
    __syncthreads();

    // Reconstruct pos_scatter for this block's 256 predictions
    if (tid < MM) {
        unsigned long long v = g_pg[b * MM + tid];
        if (v) {  // nonzero => some pred had iou > 0.1 with this gt
            unsigned idx = 0xFFFFFFFFu - (unsigned)(v & 0xFFFFFFFFull);
            if ((int)(idx >> 8) == blk) sflag[idx & 255u] = 1;
        }
    }
    __syncthreads();

    const float* p = pred + ((size_t)b * NN + n) * 5;
    const float cx = p[0], cy = p[1], w = p[2], h = p[3], obj = p[4];
    const float px1 = cx - w * 0.5f, py1 = cy - h * 0.5f;
    const float px2 = cx + w * 0.5f, py2 = cy + h * 0.5f;

    unsigned long long bgv = g_bg[(size_t)b * NN + n];
    float biou = __uint_as_float((unsigned)(bgv >> 32));
    int bidx = (int)(bgv & 0xFFFFFFFFull);

    bool pos = (sflag[tid] != 0) || (biou > 0.5f);
    bool neg = biou < 0.4f;
    bool valid = pos || neg;

    // Focal loss
    float l = obj;
    float t = pos ? 1.0f : 0.0f;
    float bce = fmaxf(l, 0.0f) - l * t + log1pf(expf(-fabsf(l)));
    float psig = 1.0f / (1.0f + expf(-l));
    float p_t = pos ? psig : 1.0f - psig;
    float alpha_t = pos ? 0.25f : 0.75f;
    float om = 1.0f - p_t;
    float fl = alpha_t * om * om * bce;

    // GIoU term vs matched gt
    float4 g = sg[bidx];
    float x1 = fmaxf(px1, g.x), y1 = fmaxf(py1, g.y);
    float x2 = fminf(px2, g.z), y2 = fminf(py2, g.w);
    float inter = fmaxf(x2 - x1, 0.0f) * fmaxf(y2 - y1, 0.0f);
    float ap = (px2 - px1) * (py2 - py1);
    float ag = (g.z - g.x) * (g.w - g.y);
    float uni = ap + ag - inter;
    float iou = inter / fmaxf(uni, EPSF);
    float ex1 = fminf(px1, g.x), ey1 = fminf(py1, g.y);
    float ex2 = fmaxf(px2, g.z), ey2 = fmaxf(py2, g.w);
    float enc = (ex2 - ex1) * (ey2 - ey1);
    float giou = iou - (enc - uni) / fmaxf(enc, EPSF);
    float gterm = 1.0f - giou;

    float flc = valid ? fl : 0.0f;
    float vc  = valid ? 1.0f : 0.0f;
    float gs  = pos ? gterm : 0.0f;
    float pc  = pos ? 1.0f : 0.0f;

    // Deterministic block reduction (fixed shuffle tree)
    __shared__ float4 sred[8];
#pragma unroll
    for (int off = 16; off; off >>= 1) {
        flc += __shfl_down_sync(0xFFFFFFFFu, flc, off);
        vc  += __shfl_down_sync(0xFFFFFFFFu, vc,  off);
        gs  += __shfl_down_sync(0xFFFFFFFFu, gs,  off);
        pc  += __shfl_down_sync(0xFFFFFFFFu, pc,  off);
    }
    int wid = tid >> 5, lane = tid & 31;
    if (lane == 0) sred[wid] = make_float4(flc, vc, gs, pc);
    __syncthreads();
    if (wid == 0) {
        float4 v = (lane < 8) ? sred[lane] : make_float4(0.f, 0.f, 0.f, 0.f);
#pragma unroll
        for (int off = 4; off; off >>= 1) {
            v.x += __shfl_down_sync(0xFFFFFFFFu, v.x, off);
            v.y += __shfl_down_sync(0xFFFFFFFFu, v.y, off);
            v.z += __shfl_down_sync(0xFFFFFFFFu, v.z, off);
            v.w += __shfl_down_sync(0xFFFFFFFFu, v.w, off);
        }
        if (lane == 0) ((float4*)g_part)[blockIdx.x] = v;
    }
}

// ---------------------------------------------------------------------------
// Reduce A: one block per batch image; fixed-tree -> per-image cls/reg/pcnt.
__global__ void __launch_bounds__(256) k_reduceA() {
    const int b = blockIdx.x;
    const int tid = threadIdx.x;
    float4 v = ((const float4*)g_part)[b * BLOCKS_PER_B + tid];

    __shared__ float4 sred[8];
#pragma unroll
    for (int off = 16; off; off >>= 1) {
        v.x += __shfl_down_sync(0xFFFFFFFFu, v.x, off);
        v.y += __shfl_down_sync(0xFFFFFFFFu, v.y, off);
        v.z += __shfl_down_sync(0xFFFFFFFFu, v.z, off);
        v.w += __shfl_down_sync(0xFFFFFFFFu, v.w, off);
    }
    int wid = tid >> 5, lane = tid & 31;
    if (lane == 0) sred[wid] = v;
    __syncthreads();
    if (wid == 0) {
        float4 u = (lane < 8) ? sred[lane] : make_float4(0.f, 0.f, 0.f, 0.f);
#pragma unroll
        for (int off = 4; off; off >>= 1) {
            u.x += __shfl_down_sync(0xFFFFFFFFu, u.x, off);
            u.y += __shfl_down_sync(0xFFFFFFFFu, u.y, off);
            u.z += __shfl_down_sync(0xFFFFFFFFu, u.z, off);
            u.w += __shfl_down_sync(0xFFFFFFFFu, u.w, off);
        }
        if (lane == 0) {
            float cls = (u.y > 0.0f) ? u.x / fmaxf(u.y, 1.0f) : 0.0f;
            float reg = (u.w > 0.0f) ? u.z / fmaxf(u.w, 1.0f) : 0.0f;
            g_bres[b] = cls;
            g_bres[BB + b] = reg;
            g_bres[2 * BB + b] = u.w;
        }
    }
}

// ---------------------------------------------------------------------------
// Reduce B: combine batches into the final scalar.
__global__ void k_reduceB(float* __restrict__ out) {
    const int t = threadIdx.x;  // 32 threads
    float cls = g_bres[t];
    float reg = g_bres[BB + t];
    float pc  = g_bres[2 * BB + t];
#pragma unroll
    for (int off = 16; off; off >>= 1) {
        cls += __shfl_down_sync(0xFFFFFFFFu, cls, off);
        reg += __shfl_down_sync(0xFFFFFFFFu, reg, off);
        pc  += __shfl_down_sync(0xFFFFFFFFu, pc,  off);
    }
    if (t == 0) {
        float num_pos = fmaxf(pc, 1.0f);
        float total_cls = cls / (float)BB;
        float total_reg = reg / num_pos * (float)BB;
        out[0] = total_cls + 2.0f * total_reg;
    }
}

// ---------------------------------------------------------------------------
extern "C" void kernel_launch(void* const* d_in, const int* in_sizes, int n_in,
                              void* d_out, int out_size) {
    const float* pred = (const float*)d_in[0];  // [B, N, 5]
    const float* gt   = (const float*)d_in[1];  // [B, M, 4]
    float* out = (float*)d_out;

    k_init<<<8, 256>>>();
    k_pass1<<<GRID_MAIN, 256>>>(pred, gt);
    k_pass2<<<GRID_MAIN, 256>>>(pred, gt);
    k_reduceA<<<BB, 256>>>();
    k_reduceB<<<1, 32>>>(out);
}

// round 4
// speedup vs baseline: 2.0051x; 2.0051x over previous
#include <cuda_runtime.h>

// Fixed problem shapes
#define BB 32
#define NN 65536
#define MM 64
#define KP 4                              // preds per thread in main passes
#define PRED_PER_BLK 1024                 // 256 threads * KP
#define BLKS_PER_B (NN / PRED_PER_BLK)    // 64
#define GRID_MAIN (BB * BLKS_PER_B)       // 2048

// Scratch (static device globals; no allocation)
__device__ unsigned long long g_pg[BB * MM];          // per-gt packed (iou_bits<<32)|(~pred_idx)
__device__ unsigned char g_tag[(size_t)BB * NN];      // per-pred: bestM | pos<<6 | neg<<7
__device__ float4 g_part[GRID_MAIN];                  // per-block partials (fl, vcnt, gsum, pcnt)

// ---------------------------------------------------------------------------
__global__ void k_init() {
    int i = blockIdx.x * blockDim.x + threadIdx.x;
    if (i < BB * MM) g_pg[i] = 0ull;
}

// ---------------------------------------------------------------------------
// Pass 1: pairwise IoU, 4 preds per thread, GTs in shared.
__global__ void __launch_bounds__(256) k_pass1(const float* __restrict__ pred,
                                               const float* __restrict__ gt) {
    const int b   = blockIdx.x >> 6;
    const int blk = blockIdx.x & 63;
    const int tid = threadIdx.x;
    const int n0  = (blk << 10) + tid;

    __shared__ float4 sg[MM];
    __shared__ float sa[MM];
    __shared__ unsigned long long smax[MM];

    if (tid < MM) {
        float4 g = ((const float4*)(gt + (size_t)b * MM * 4))[tid];
        sg[tid] = g;
        sa[tid] = (g.z - g.x) * (g.w - g.y);
        smax[tid] = 0ull;
    }
    __syncthreads();

    float px1[KP], py1[KP], px2[KP], py2[KP], pa[KP], bi[KP];
    int bm[KP];
    unsigned pl[KP];
#pragma unroll
    for (int k = 0; k < KP; ++k) {
        const float* p = pred + ((size_t)b * NN + n0 + (k << 8)) * 5;
        float cx = p[0], cy = p[1], w = p[2], h = p[3];
        px1[k] = cx - w * 0.5f; py1[k] = cy - h * 0.5f;
        px2[k] = cx + w * 0.5f; py2[k] = cy + h * 0.5f;
        pa[k]  = (px2[k] - px1[k]) * (py2[k] - py1[k]);  // match reference form
        bi[k]  = -1.0f;
        bm[k]  = 0;
        pl[k]  = 0xFFFFFFFFu - (unsigned)(n0 + (k << 8)); // smaller n wins ties
    }

#pragma unroll 4
    for (int m = 0; m < MM; ++m) {
        float4 g = sg[m];
        float ga = sa[m];
#pragma unroll
        for (int k = 0; k < KP; ++k) {
            float x1 = fmaxf(px1[k], g.x);
            float y1 = fmaxf(py1[k], g.y);
            float x2 = fminf(px2[k], g.z);
            float y2 = fminf(py2[k], g.w);
            float iw = fmaxf(x2 - x1, 0.0f);
            float ih = fmaxf(y2 - y1, 0.0f);
            float inter = iw * ih;
            // union >= max(area_p, area_g) >= 64 >> eps, so no clamp needed
            float uni = (pa[k] + ga) - inter;
            float iou = __fdividef(inter, uni);
            if (iou > bi[k]) bm[k] = m;        // strict > keeps first max (argmax)
            bi[k] = fmaxf(bi[k], iou);
            if (iou > 0.1f)                    // only such pairs affect pos_scatter
                atomicMax(&smax[m],
                    ((unsigned long long)__float_as_uint(iou) << 32) | pl[k]);
        }
    }

#pragma unroll
    for (int k = 0; k < KP; ++k) {
        unsigned tag = (unsigned)bm[k];
        if (bi[k] > 0.5f) tag |= 0x40u;   // best_gt_per_pred > POS_THR
        if (bi[k] < 0.4f) tag |= 0x80u;   // best_gt_per_pred < NEG_THR
        g_tag[(size_t)b * NN + n0 + (k << 8)] = (unsigned char)tag;
    }

    __syncthreads();
    if (tid < MM && smax[tid])
        atomicMax(&g_pg[b * MM + tid], smax[tid]);
}

// ---------------------------------------------------------------------------
// Pass 2: focal + GIoU, 4 preds per thread, deterministic block reduction.
__global__ void __launch_bounds__(256) k_pass2(const float* __restrict__ pred,
                                               const float* __restrict__ gt) {
    const int b   = blockIdx.x >> 6;
    const int blk = blockIdx.x & 63;
    const int tid = threadIdx.x;
    const int n0  = (blk << 10) + tid;

    __shared__ float4 sg[MM];
    __shared__ unsigned char sflag[PRED_PER_BLK];

#pragma unroll
    for (int k = 0; k < KP; ++k) sflag[tid + (k << 8)] = 0;
    if (tid < MM) sg[tid] = ((const float4*)(gt + (size_t)b * MM * 4))[tid];
    __syncthreads();

    // Decode per-gt winners into this block's pos_scatter flags
    if (tid < MM) {
        unsigned long long v = g_pg[b * MM + tid];
        if (v) {  // nonzero => best iou for this gt exceeded 0.1
            unsigned idx = 0xFFFFFFFFu - (unsigned)(v & 0xFFFFFFFFull);
            if ((int)(idx >> 10) == blk) sflag[idx & 1023u] = 1;
        }
    }
    __syncthreads();

    float facc = 0.0f, vacc = 0.0f, gacc = 0.0f, pacc = 0.0f;
#pragma unroll
    for (int k = 0; k < KP; ++k) {
        const int n = n0 + (k << 8);
        const float* p = pred + ((size_t)b * NN + n) * 5;
        float cx = p[0], cy = p[1], w = p[2], h = p[3], obj = p[4];
        float px1 = cx - w * 0.5f, py1 = cy - h * 0.5f;
        float px2 = cx + w * 0.5f, py2 = cy + h * 0.5f;

        unsigned tag = g_tag[(size_t)b * NN + n];
        int bidx = (int)(tag & 63u);
        bool pos = (sflag[tid + (k << 8)] != 0) || (tag & 0x40u);
        bool neg = (tag & 0x80u) != 0;
        bool valid = pos || neg;

        // Focal loss (single expf: sigmoid via q = e^{-|l|})
        float l = obj;
        float q = expf(-fabsf(l));
        float s = 1.0f / (1.0f + q);               // = sigmoid(|l|)
        float bce = fmaxf(l, 0.0f) - (pos ? l : 0.0f) + log1pf(q);
        bool flip = (pos == (l >= 0.0f));          // p_t = flip ? s : 1-s
        float p_t = flip ? s : 1.0f - s;
        float om = 1.0f - p_t;
        float alpha_t = pos ? 0.25f : 0.75f;
        float fl = alpha_t * om * om * bce;

        // GIoU term vs matched gt
        float4 g = sg[bidx];
        float x1 = fmaxf(px1, g.x), y1 = fmaxf(py1, g.y);
        float x2 = fminf(px2, g.z), y2 = fminf(py2, g.w);
        float inter = fmaxf(x2 - x1, 0.0f) * fmaxf(y2 - y1, 0.0f);
        float ap = (px2 - px1) * (py2 - py1);
        float ag = (g.z - g.x) * (g.w - g.y);
        float uni = ap + ag - inter;               // >= 64 > eps
        float iou = __fdividef(inter, uni);
        float ex1 = fminf(px1, g.x), ey1 = fminf(py1, g.y);
        float ex2 = fmaxf(px2, g.z), ey2 = fmaxf(py2, g.w);
        float enc = (ex2 - ex1) * (ey2 - ey1);     // >= union > eps
        float gterm = 1.0f - (iou - __fdividef(enc - uni, enc));

        if (valid) { facc += fl; vacc += 1.0f; }
        if (pos)   { gacc += gterm; pacc += 1.0f; }
    }

    // Deterministic block reduction (fixed shuffle tree)
    __shared__ float4 sred[8];
#pragma unroll
    for (int off = 16; off; off >>= 1) {
        facc += __shfl_down_sync(0xFFFFFFFFu, facc, off);
        vacc += __shfl_down_sync(0xFFFFFFFFu, vacc, off);
        gacc += __shfl_down_sync(0xFFFFFFFFu, gacc, off);
        pacc += __shfl_down_sync(0xFFFFFFFFu, pacc, off);
    }
    int wid = tid >> 5, lane = tid & 31;
    if (lane == 0) sred[wid] = make_float4(facc, vacc, gacc, pacc);
    __syncthreads();
    if (wid == 0) {
        float4 v = (lane < 8) ? sred[lane] : make_float4(0.f, 0.f, 0.f, 0.f);
#pragma unroll
        for (int off = 4; off; off >>= 1) {
            v.x += __shfl_down_sync(0xFFFFFFFFu, v.x, off);
            v.y += __shfl_down_sync(0xFFFFFFFFu, v.y, off);
            v.z += __shfl_down_sync(0xFFFFFFFFu, v.z, off);
            v.w += __shfl_down_sync(0xFFFFFFFFu, v.w, off);
        }
        if (lane == 0) g_part[blockIdx.x] = v;
    }
}

// ---------------------------------------------------------------------------
// Final: one block, warp w reduces image w's 64 partials, then warp 0 combines.
__global__ void __launch_bounds__(1024) k_final(float* __restrict__ out) {
    const int tid = threadIdx.x;
    const int wid = tid >> 5, lane = tid & 31;
    __shared__ float scls[32], sreg[32], spc[32];

    float4 v = g_part[wid * 64 + lane];
    float4 u = g_part[wid * 64 + 32 + lane];
    v.x += u.x; v.y += u.y; v.z += u.z; v.w += u.w;
#pragma unroll
    for (int off = 16; off; off >>= 1) {
        v.x += __shfl_down_sync(0xFFFFFFFFu, v.x, off);
        v.y += __shfl_down_sync(0xFFFFFFFFu, v.y, off);
        v.z += __shfl_down_sync(0xFFFFFFFFu, v.z, off);
        v.w += __shfl_down_sync(0xFFFFFFFFu, v.w, off);
    }
    if (lane == 0) {
        scls[wid] = (v.y > 0.0f) ? v.x / fmaxf(v.y, 1.0f) : 0.0f;
        sreg[wid] = (v.w > 0.0f) ? v.z / fmaxf(v.w, 1.0f) : 0.0f;
        spc[wid]  = v.w;
    }
    __syncthreads();
    if (wid == 0) {
        float cls = scls[lane], reg = sreg[lane], pc = spc[lane];
#pragma unroll
        for (int off = 16; off; off >>= 1) {
            cls += __shfl_down_sync(0xFFFFFFFFu, cls, off);
            reg += __shfl_down_sync(0xFFFFFFFFu, reg, off);
            pc  += __shfl_down_sync(0xFFFFFFFFu, pc,  off);
        }
        if (lane == 0) {
            float num_pos = fmaxf(pc, 1.0f);
            out[0] = cls / (float)BB + 2.0f * (reg / num_pos * (float)BB);
        }
    }
}

// ---------------------------------------------------------------------------
extern "C" void kernel_launch(void* const* d_in, const int* in_sizes, int n_in,
                              void* d_out, int out_size) {
    const float* pred = (const float*)d_in[0];  // [B, N, 5]
    const float* gt   = (const float*)d_in[1];  // [B, M, 4]
    float* out = (float*)d_out;

    k_init<<<2, 1024>>>();
    k_pass1<<<GRID_MAIN, 256>>>(pred, gt);
    k_pass2<<<GRID_MAIN, 256>>>(pred, gt);
    k_final<<<1, 1024>>>(out);
}